// round 1
// baseline (speedup 1.0000x reference)
#include <cuda_runtime.h>
#include <cuda_bf16.h>
#include <math.h>

// Problem constants
#define NTOK 16384   // B*T = 8*2048
#define DM   512
#define RHM  1024    // 2*D
#define HM   2048    // 4*D
#define EM   8
#define TOPK 4

// ---------------- scratch (static device globals, zero-initialized) ----------
__device__ float    g_bufA[(size_t)NTOK * HM];
__device__ float    g_bufB[(size_t)NTOK * HM];
__device__ float    g_bufC[(size_t)NTOK * HM];
__device__ float    g_logits[(size_t)NTOK * EM];
__device__ unsigned g_mask[NTOK];
__device__ int      g_idx[EM * NTOK];
__device__ int      g_cnt[EM];

// ---------------- tiled fp32 GEMM ------------------------------------------
// C[M, Ncols] = A[M, K] @ B[K, Ncols] + bias[Ncols]
// Block tile 128x128, K-step 8, 256 threads, 8x8 per thread.
// GATHER:  A row m is x[gidx[m]]
// SCATTER: epilogue does C[gidx[m]*Ncols + n] += (acc + bias[n]) * scale
// mcnt: device pointer to dynamic M (or nullptr -> NTOK). Grid is sized for
// the worst case; tiles beyond M exit immediately (graph-capture friendly).
template <bool GATHER, bool SCATTER>
__global__ void __launch_bounds__(256)
sgemm_kernel(const float* __restrict__ A, const float* __restrict__ B,
             const float* __restrict__ bias, float* __restrict__ C,
             int K, int Ncols,
             const int* __restrict__ mcnt, const int* __restrict__ gidx,
             float scale)
{
    const int M = mcnt ? *mcnt : NTOK;
    const int m0 = blockIdx.y * 128;
    if (m0 >= M) return;
    const int n0 = blockIdx.x * 128;

    __shared__ float As[8][128];
    __shared__ float Bs[8][128];

    const int tid = threadIdx.x;
    // A-tile loading: each thread loads one float4 (row = tid/2, 4 cols)
    const int ar = tid >> 1;
    const int ac = (tid & 1) * 4;
    // B-tile loading: row = tid/32, 4 cols
    const int br = tid >> 5;
    const int bc = (tid & 31) * 4;

    long arow;
    bool arow_ok = true;
    if (GATHER) {
        const int mr = m0 + ar;
        if (mr < M) arow = gidx[mr];
        else { arow = 0; arow_ok = false; }
    } else {
        arow = m0 + ar;   // buffers are sized NTOK rows: always in-bounds
    }

    const int tx = tid & 15;   // column group
    const int ty = tid >> 4;   // row group

    float acc[8][8];
#pragma unroll
    for (int i = 0; i < 8; i++)
#pragma unroll
        for (int j = 0; j < 8; j++) acc[i][j] = 0.f;

    const float* Abase = A + arow * (long)K + ac;
    for (int k0 = 0; k0 < K; k0 += 8) {
        float4 av;
        if (!GATHER || arow_ok) av = *(const float4*)(Abase + k0);
        else av = make_float4(0.f, 0.f, 0.f, 0.f);
        As[ac + 0][ar] = av.x;
        As[ac + 1][ar] = av.y;
        As[ac + 2][ar] = av.z;
        As[ac + 3][ar] = av.w;

        const float4 bv = *(const float4*)(B + (long)(k0 + br) * Ncols + n0 + bc);
        *(float4*)&Bs[br][bc] = bv;
        __syncthreads();

#pragma unroll
        for (int kk = 0; kk < 8; kk++) {
            float a[8], b[8];
#pragma unroll
            for (int i = 0; i < 8; i++) a[i] = As[kk][ty * 8 + i];
#pragma unroll
            for (int j = 0; j < 8; j++) b[j] = Bs[kk][tx * 8 + j];
#pragma unroll
            for (int i = 0; i < 8; i++)
#pragma unroll
                for (int j = 0; j < 8; j++) acc[i][j] = fmaf(a[i], b[j], acc[i][j]);
        }
        __syncthreads();
    }

#pragma unroll
    for (int i = 0; i < 8; i++) {
        const int m = m0 + ty * 8 + i;
        if (m >= M) continue;
        if (SCATTER) {
            const long tok = gidx[m];
            float* orow = C + tok * (long)Ncols + n0 + tx * 8;
            const float* brow = bias + n0 + tx * 8;
#pragma unroll
            for (int j = 0; j < 8; j++)
                orow[j] += (acc[i][j] + brow[j]) * scale;
        } else {
            float* crow = C + (long)m * Ncols + n0 + tx * 8;
            const float* brow = bias + n0 + tx * 8;
#pragma unroll
            for (int j = 0; j < 8; j++)
                crow[j] = acc[i][j] + brow[j];
        }
    }
}

// ---------------- small kernels ---------------------------------------------

// logits[t, e] = rh2[t, :] @ r_out_w[:, e] + r_out_b[e]   (RH=1024, E=8)
__global__ void __launch_bounds__(256)
logits_kernel(const float* __restrict__ rh, const float* __restrict__ W,
              const float* __restrict__ b, float* __restrict__ logits)
{
    const int t = blockIdx.x;
    const float* row = rh + (long)t * RHM;
    float p[EM];
#pragma unroll
    for (int e = 0; e < EM; e++) p[e] = 0.f;
    for (int k = threadIdx.x; k < RHM; k += 256) {
        const float v = row[k];
        const float* wr = W + (long)k * EM;
#pragma unroll
        for (int e = 0; e < EM; e++) p[e] = fmaf(v, wr[e], p[e]);
    }
    // warp reduce
#pragma unroll
    for (int e = 0; e < EM; e++)
#pragma unroll
        for (int off = 16; off > 0; off >>= 1)
            p[e] += __shfl_down_sync(0xffffffffu, p[e], off);
    __shared__ float red[EM][8];
    const int lane = threadIdx.x & 31, warp = threadIdx.x >> 5;
    if (lane == 0)
#pragma unroll
        for (int e = 0; e < EM; e++) red[e][warp] = p[e];
    __syncthreads();
    if (threadIdx.x < EM) {
        float s = b[threadIdx.x];
#pragma unroll
        for (int w = 0; w < 8; w++) s += red[threadIdx.x][w];
        logits[(long)t * EM + threadIdx.x] = s;
    }
}

// top-4 of 8 logits (softmax is monotonic -> operate on logits directly)
__global__ void topk_kernel(const float* __restrict__ logits,
                            unsigned* __restrict__ maskb)
{
    const int t = blockIdx.x * blockDim.x + threadIdx.x;
    if (t >= NTOK) return;
    float v[EM];
#pragma unroll
    for (int e = 0; e < EM; e++) v[e] = logits[(long)t * EM + e];
    unsigned m = 0;
#pragma unroll
    for (int s = 0; s < TOPK; s++) {
        int best = 0;
        float bv = -INFINITY;
#pragma unroll
        for (int e = 0; e < EM; e++) {
            if (!((m >> e) & 1u) && v[e] > bv) { bv = v[e]; best = e; }
        }
        m |= 1u << best;
    }
    maskb[t] = m;
}

// per-expert index compaction, in token order (deterministic)
__global__ void __launch_bounds__(256)
compact_kernel(const unsigned* __restrict__ maskb,
               int* __restrict__ idx, int* __restrict__ cnt)
{
    const int e = blockIdx.x;
    __shared__ int s_base;
    __shared__ int s_warp[8];
    if (threadIdx.x == 0) s_base = 0;
    __syncthreads();
    const int lane = threadIdx.x & 31, warp = threadIdx.x >> 5;
    for (int c = 0; c < NTOK; c += 256) {
        const int t = c + threadIdx.x;
        const int p = (maskb[t] >> e) & 1u;
        const unsigned bal = __ballot_sync(0xffffffffu, p);
        if (lane == 0) s_warp[warp] = __popc(bal);
        __syncthreads();
        int woff = 0, tot = 0;
        for (int w = 0; w < 8; w++) { if (w < warp) woff += s_warp[w]; tot += s_warp[w]; }
        const int rank = __popc(bal & ((1u << lane) - 1u));
        if (p) idx[e * NTOK + s_base + woff + rank] = t;
        __syncthreads();
        if (threadIdx.x == 0) s_base += tot;
        __syncthreads();
    }
    if (threadIdx.x == 0) cnt[e] = s_base;
}

// out = silu(h1) * h2 elementwise over [*mcnt, width]
__global__ void silu_mul_kernel(const float* __restrict__ h1,
                                const float* __restrict__ h2,
                                float* __restrict__ out,
                                int width, const int* __restrict__ mcnt)
{
    const long total = (long)(mcnt ? *mcnt : NTOK) * width;
    const long stride = (long)gridDim.x * blockDim.x;
    for (long i = (long)blockIdx.x * blockDim.x + threadIdx.x; i < total; i += stride) {
        const float a = h1[i];
        const float s = a / (1.f + expf(-a));
        out[i] = s * h2[i];
    }
}

__global__ void zero_kernel(float* __restrict__ out, long n)
{
    const long stride = (long)gridDim.x * blockDim.x;
    for (long i = (long)blockIdx.x * blockDim.x + threadIdx.x; i < n; i += stride)
        out[i] = 0.f;
}

// ---------------- launcher ---------------------------------------------------
extern "C" void kernel_launch(void* const* d_in, const int* in_sizes, int n_in,
                              void* d_out, int out_size)
{
    const float* x       = (const float*)d_in[0];
    const float* r_in_w  = (const float*)d_in[1];
    const float* r_in_b  = (const float*)d_in[2];
    const float* rs_w1   = (const float*)d_in[3];
    const float* rs_b1   = (const float*)d_in[4];
    const float* rs_w2   = (const float*)d_in[5];
    const float* rs_b2   = (const float*)d_in[6];
    const float* rs_w3   = (const float*)d_in[7];
    const float* rs_b3   = (const float*)d_in[8];
    const float* r_out_w = (const float*)d_in[9];
    const float* r_out_b = (const float*)d_in[10];
    const float* e_in_w  = (const float*)d_in[11];
    const float* e_in_b  = (const float*)d_in[12];
    const float* es_w1   = (const float*)d_in[13];
    const float* es_b1   = (const float*)d_in[14];
    const float* es_w2   = (const float*)d_in[15];
    const float* es_b2   = (const float*)d_in[16];
    const float* es_w3   = (const float*)d_in[17];
    const float* es_b3   = (const float*)d_in[18];
    const float* e_out_w = (const float*)d_in[19];
    const float* e_out_b = (const float*)d_in[20];
    float* out = (float*)d_out;

    float *bufA, *bufB, *bufC, *logits;
    unsigned* maskb;
    int *idx, *cnt;
    cudaGetSymbolAddress((void**)&bufA,   g_bufA);
    cudaGetSymbolAddress((void**)&bufB,   g_bufB);
    cudaGetSymbolAddress((void**)&bufC,   g_bufC);
    cudaGetSymbolAddress((void**)&logits, g_logits);
    cudaGetSymbolAddress((void**)&maskb,  g_mask);
    cudaGetSymbolAddress((void**)&idx,    g_idx);
    cudaGetSymbolAddress((void**)&cnt,    g_cnt);

    const dim3 blk(256);
    const dim3 gridRouter(RHM / 128, NTOK / 128);   // 8 x 128
    const dim3 gridEH(HM / 128, NTOK / 128);        // 16 x 128
    const dim3 gridEO(DM / 128, NTOK / 128);        // 4 x 128

    // ---- router ----
    sgemm_kernel<false, false><<<gridRouter, blk>>>(x, r_in_w, r_in_b, bufA,
                                                    DM, RHM, nullptr, nullptr, 1.f);
    sgemm_kernel<false, false><<<gridRouter, blk>>>(bufA, rs_w1, rs_b1, bufB,
                                                    RHM, RHM, nullptr, nullptr, 1.f);
    sgemm_kernel<false, false><<<gridRouter, blk>>>(bufA, rs_w2, rs_b2, bufC,
                                                    RHM, RHM, nullptr, nullptr, 1.f);
    silu_mul_kernel<<<2048, blk>>>(bufB, bufC, bufB, RHM, nullptr);
    sgemm_kernel<false, false><<<gridRouter, blk>>>(bufB, rs_w3, rs_b3, bufA,
                                                    RHM, RHM, nullptr, nullptr, 1.f);
    logits_kernel<<<NTOK, blk>>>(bufA, r_out_w, r_out_b, logits);
    topk_kernel<<<NTOK / 256, blk>>>(logits, maskb);
    compact_kernel<<<EM, blk>>>(maskb, idx, cnt);

    // ---- output init ----
    zero_kernel<<<1024, blk>>>(out, (long)NTOK * DM);

    // ---- experts (selected tokens only) ----
    for (int e = 0; e < EM; e++) {
        const int* ce = cnt + e;
        const int* ie = idx + e * NTOK;
        // h = gather(x) @ e_in_w[e] + e_in_b[e]        -> bufA [n_e, H]
        sgemm_kernel<true, false><<<gridEH, blk>>>(
            x, e_in_w + (long)e * DM * HM, e_in_b + (long)e * HM, bufA,
            DM, HM, ce, ie, 1.f);
        // h1 = bufA @ es_w1[e] + b1 -> bufB ; h2 = bufA @ es_w2[e] + b2 -> bufC
        sgemm_kernel<false, false><<<gridEH, blk>>>(
            bufA, es_w1 + (long)e * HM * HM, es_b1 + (long)e * HM, bufB,
            HM, HM, ce, nullptr, 1.f);
        sgemm_kernel<false, false><<<gridEH, blk>>>(
            bufA, es_w2 + (long)e * HM * HM, es_b2 + (long)e * HM, bufC,
            HM, HM, ce, nullptr, 1.f);
        // hs = silu(h1) * h2 -> bufB
        silu_mul_kernel<<<2048, blk>>>(bufB, bufC, bufB, HM, ce);
        // hs @ es_w3[e] + b3 -> bufA
        sgemm_kernel<false, false><<<gridEH, blk>>>(
            bufB, es_w3 + (long)e * HM * HM, es_b3 + (long)e * HM, bufA,
            HM, HM, ce, nullptr, 1.f);
        // out[tok] += (bufA @ e_out_w[e] + e_out_b[e]) / E   (scatter)
        sgemm_kernel<false, true><<<gridEO, blk>>>(
            bufA, e_out_w + (long)e * HM * DM, e_out_b + (long)e * DM, out,
            HM, DM, ce, ie, 1.f / EM);
    }
}

// round 2
// speedup vs baseline: 2.1349x; 2.1349x over previous
#include <cuda_runtime.h>
#include <cuda_bf16.h>
#include <math.h>
#include <stdint.h>

// Problem constants
#define NTOK 16384   // B*T = 8*2048
#define DM   512
#define RHM  1024    // 2*D
#define HM   2048    // 4*D
#define EM   8
#define TOPK 4

// ---------------- scratch (static device globals) ---------------------------
__device__ float    g_bufA[(size_t)NTOK * HM];
__device__ float    g_bufB[(size_t)NTOK * HM];
__device__ float    g_bufC[(size_t)NTOK * HM];
__device__ float    g_logits[(size_t)NTOK * EM];
__device__ unsigned g_mask[NTOK];
__device__ int      g_idx[EM * NTOK];
__device__ int      g_cnt[EM];

// ---------------- helpers ----------------------------------------------------
__device__ __forceinline__ uint32_t smem_u32(const void* p) {
    return (uint32_t)__cvta_generic_to_shared(p);
}

__device__ __forceinline__ void ldm_x4(uint32_t* r, uint32_t addr) {
    asm volatile("ldmatrix.sync.aligned.m8n8.x4.shared.b16 {%0,%1,%2,%3},[%4];"
                 : "=r"(r[0]), "=r"(r[1]), "=r"(r[2]), "=r"(r[3]) : "r"(addr));
}
__device__ __forceinline__ void ldm_x4t(uint32_t* r, uint32_t addr) {
    asm volatile("ldmatrix.sync.aligned.m8n8.x4.trans.shared.b16 {%0,%1,%2,%3},[%4];"
                 : "=r"(r[0]), "=r"(r[1]), "=r"(r[2]), "=r"(r[3]) : "r"(addr));
}
__device__ __forceinline__ void mma16816(float* d, const uint32_t* a, const uint32_t* b) {
    asm volatile(
        "mma.sync.aligned.m16n8k16.row.col.f32.bf16.bf16.f32 "
        "{%0,%1,%2,%3},{%4,%5,%6,%7},{%8,%9},{%0,%1,%2,%3};"
        : "+f"(d[0]), "+f"(d[1]), "+f"(d[2]), "+f"(d[3])
        : "r"(a[0]), "r"(a[1]), "r"(a[2]), "r"(a[3]), "r"(b[0]), "r"(b[1]));
}

__device__ __forceinline__ uint32_t pack_bf2(__nv_bfloat16 a, __nv_bfloat16 b) {
    return (uint32_t)__bfloat16_as_ushort(a) | ((uint32_t)__bfloat16_as_ushort(b) << 16);
}

// split fp32 -> (hi, lo) bf16 pair
__device__ __forceinline__ void split1(float v, __nv_bfloat16& h, __nv_bfloat16& l) {
    h = __float2bfloat16(v);
    l = __float2bfloat16(v - __bfloat162float(h));
}

// ---------------- 3xBF16 tensor-core GEMM -----------------------------------
// C[M, Ncols] = A[M, K] @ B[K, Ncols] + bias  (fp32 in/out, split-bf16 mma)
// BM=128, BN=128, BK=32, 256 threads, 8 warps (warp tile 64x32).
template <bool GATHER, bool SCATTER>
__global__ void __launch_bounds__(256)
mma_gemm_kernel(const float* __restrict__ A, const float* __restrict__ B,
                const float* __restrict__ bias, float* __restrict__ C,
                int K, int Ncols,
                const int* __restrict__ mcnt, const int* __restrict__ gidx,
                float scale)
{
    const int M = mcnt ? *mcnt : NTOK;
    const int m0 = blockIdx.y * 128;
    if (m0 >= M) return;
    const int n0 = blockIdx.x * 128;

    __shared__ __align__(16) __nv_bfloat16 AsH[128][40];
    __shared__ __align__(16) __nv_bfloat16 AsL[128][40];
    __shared__ __align__(16) __nv_bfloat16 BsH[32][136];
    __shared__ __align__(16) __nv_bfloat16 BsL[32][136];

    const int tid  = threadIdx.x;
    const int lane = tid & 31;
    const int wid  = tid >> 5;
    const int wm   = wid >> 2;   // 0..1  (64-row slab)
    const int wn   = wid & 3;    // 0..3  (32-col slab)

    // ---- global load setup (4 float4 of A, 4 of B per thread per BK) ----
    const float* aptr[4];
    int ar_s[4], ac_s[4];
#pragma unroll
    for (int i = 0; i < 4; i++) {
        const int idx = i * 256 + tid;
        const int r = idx >> 3;          // 0..127
        const int c4 = (idx & 7) * 4;    // 0..28
        ar_s[i] = r; ac_s[i] = c4;
        long row;
        if (GATHER) {
            const int m = m0 + r;
            row = (m < M) ? (long)gidx[m] : 0;
        } else {
            row = m0 + r;
        }
        aptr[i] = A + row * (long)K + c4;
    }
    const float* bptr[4];
    int br_s[4], bc_s[4];
#pragma unroll
    for (int i = 0; i < 4; i++) {
        const int idx = i * 256 + tid;
        const int r = idx >> 5;          // 0..31
        const int c4 = (idx & 31) * 4;   // 0..124
        br_s[i] = r; bc_s[i] = c4;
        bptr[i] = B + (long)r * Ncols + n0 + c4;
    }

    float acc[4][4][4];
#pragma unroll
    for (int mi = 0; mi < 4; mi++)
#pragma unroll
        for (int ni = 0; ni < 4; ni++)
#pragma unroll
            for (int q = 0; q < 4; q++) acc[mi][ni][q] = 0.f;

    // smem base addresses for fragment loads
    const uint32_t aH_base = smem_u32(&AsH[wm * 64 + (lane & 15)][(lane >> 4) * 8]);
    const uint32_t aL_base = smem_u32(&AsL[wm * 64 + (lane & 15)][(lane >> 4) * 8]);
    const uint32_t bH_base = smem_u32(&BsH[(lane & 15)][wn * 32 + (lane >> 4) * 8]);
    const uint32_t bL_base = smem_u32(&BsL[(lane & 15)][wn * 32 + (lane >> 4) * 8]);

    float4 pa[4], pb[4];

    auto load_g = [&](int k0) {
#pragma unroll
        for (int i = 0; i < 4; i++) pa[i] = *(const float4*)(aptr[i] + k0);
#pragma unroll
        for (int i = 0; i < 4; i++) pb[i] = *(const float4*)(bptr[i] + (long)k0 * Ncols);
    };

    auto sts = [&]() {
#pragma unroll
        for (int i = 0; i < 4; i++) {
            __nv_bfloat16 h0, h1, h2, h3, l0, l1, l2, l3;
            split1(pa[i].x, h0, l0); split1(pa[i].y, h1, l1);
            split1(pa[i].z, h2, l2); split1(pa[i].w, h3, l3);
            uint2 hv = make_uint2(pack_bf2(h0, h1), pack_bf2(h2, h3));
            uint2 lv = make_uint2(pack_bf2(l0, l1), pack_bf2(l2, l3));
            *(uint2*)&AsH[ar_s[i]][ac_s[i]] = hv;
            *(uint2*)&AsL[ar_s[i]][ac_s[i]] = lv;
        }
#pragma unroll
        for (int i = 0; i < 4; i++) {
            __nv_bfloat16 h0, h1, h2, h3, l0, l1, l2, l3;
            split1(pb[i].x, h0, l0); split1(pb[i].y, h1, l1);
            split1(pb[i].z, h2, l2); split1(pb[i].w, h3, l3);
            uint2 hv = make_uint2(pack_bf2(h0, h1), pack_bf2(h2, h3));
            uint2 lv = make_uint2(pack_bf2(l0, l1), pack_bf2(l2, l3));
            *(uint2*)&BsH[br_s[i]][bc_s[i]] = hv;
            *(uint2*)&BsL[br_s[i]][bc_s[i]] = lv;
        }
    };

    const int nIter = K / 32;
    load_g(0);
    sts();
    __syncthreads();

    for (int it = 0; it < nIter; ++it) {
        if (it + 1 < nIter) load_g((it + 1) * 32);

#pragma unroll
        for (int k16 = 0; k16 < 32; k16 += 16) {
            uint32_t ah[4][4], al[4][4], bh[4][2], bl[4][2];
#pragma unroll
            for (int mi = 0; mi < 4; mi++) {
                const uint32_t off = (uint32_t)(mi * 16 * 40 + k16) * 2;
                ldm_x4(ah[mi], aH_base + off);
                ldm_x4(al[mi], aL_base + off);
            }
#pragma unroll
            for (int p = 0; p < 2; p++) {
                const uint32_t off = (uint32_t)(k16 * 136 + p * 16) * 2;
                uint32_t r[4];
                ldm_x4t(r, bH_base + off);
                bh[2 * p][0] = r[0]; bh[2 * p][1] = r[1];
                bh[2 * p + 1][0] = r[2]; bh[2 * p + 1][1] = r[3];
                ldm_x4t(r, bL_base + off);
                bl[2 * p][0] = r[0]; bl[2 * p][1] = r[1];
                bl[2 * p + 1][0] = r[2]; bl[2 * p + 1][1] = r[3];
            }
#pragma unroll
            for (int mi = 0; mi < 4; mi++)
#pragma unroll
                for (int ni = 0; ni < 4; ni++) {
                    mma16816(acc[mi][ni], ah[mi], bh[ni]);
                    mma16816(acc[mi][ni], ah[mi], bl[ni]);
                    mma16816(acc[mi][ni], al[mi], bh[ni]);
                }
        }
        __syncthreads();
        if (it + 1 < nIter) {
            sts();
            __syncthreads();
        }
    }

    // ---- epilogue ----
    const int gid = lane >> 2;
    const int qid = lane & 3;
#pragma unroll
    for (int mi = 0; mi < 4; mi++) {
#pragma unroll
        for (int half = 0; half < 2; half++) {
            const int m = m0 + wm * 64 + mi * 16 + gid + half * 8;
            if (m >= M) continue;
            long orow;
            if (SCATTER) orow = (long)gidx[m] * Ncols;
            else         orow = (long)m * Ncols;
#pragma unroll
            for (int ni = 0; ni < 4; ni++) {
                const int col = n0 + wn * 32 + ni * 8 + qid * 2;
                const float v0 = acc[mi][ni][half * 2 + 0];
                const float v1 = acc[mi][ni][half * 2 + 1];
                if (SCATTER) {
                    C[orow + col]     += (v0 + bias[col])     * scale;
                    C[orow + col + 1] += (v1 + bias[col + 1]) * scale;
                } else {
                    C[orow + col]     = v0 + bias[col];
                    C[orow + col + 1] = v1 + bias[col + 1];
                }
            }
        }
    }
}

// ---------------- small kernels ---------------------------------------------

__global__ void __launch_bounds__(256)
logits_kernel(const float* __restrict__ rh, const float* __restrict__ W,
              const float* __restrict__ b, float* __restrict__ logits)
{
    const int t = blockIdx.x;
    const float* row = rh + (long)t * RHM;
    float p[EM];
#pragma unroll
    for (int e = 0; e < EM; e++) p[e] = 0.f;
    for (int k = threadIdx.x; k < RHM; k += 256) {
        const float v = row[k];
        const float* wr = W + (long)k * EM;
#pragma unroll
        for (int e = 0; e < EM; e++) p[e] = fmaf(v, wr[e], p[e]);
    }
#pragma unroll
    for (int e = 0; e < EM; e++)
#pragma unroll
        for (int off = 16; off > 0; off >>= 1)
            p[e] += __shfl_down_sync(0xffffffffu, p[e], off);
    __shared__ float red[EM][8];
    const int lane = threadIdx.x & 31, warp = threadIdx.x >> 5;
    if (lane == 0)
#pragma unroll
        for (int e = 0; e < EM; e++) red[e][warp] = p[e];
    __syncthreads();
    if (threadIdx.x < EM) {
        float s = b[threadIdx.x];
#pragma unroll
        for (int w = 0; w < 8; w++) s += red[threadIdx.x][w];
        logits[(long)t * EM + threadIdx.x] = s;
    }
}

__global__ void topk_kernel(const float* __restrict__ logits,
                            unsigned* __restrict__ maskb)
{
    const int t = blockIdx.x * blockDim.x + threadIdx.x;
    if (t >= NTOK) return;
    float v[EM];
#pragma unroll
    for (int e = 0; e < EM; e++) v[e] = logits[(long)t * EM + e];
    unsigned m = 0;
#pragma unroll
    for (int s = 0; s < TOPK; s++) {
        int best = 0;
        float bv = -INFINITY;
#pragma unroll
        for (int e = 0; e < EM; e++) {
            if (!((m >> e) & 1u) && v[e] > bv) { bv = v[e]; best = e; }
        }
        m |= 1u << best;
    }
    maskb[t] = m;
}

__global__ void __launch_bounds__(256)
compact_kernel(const unsigned* __restrict__ maskb,
               int* __restrict__ idx, int* __restrict__ cnt)
{
    const int e = blockIdx.x;
    __shared__ int s_base;
    __shared__ int s_warp[8];
    if (threadIdx.x == 0) s_base = 0;
    __syncthreads();
    const int lane = threadIdx.x & 31, warp = threadIdx.x >> 5;
    for (int c = 0; c < NTOK; c += 256) {
        const int t = c + threadIdx.x;
        const int p = (maskb[t] >> e) & 1u;
        const unsigned bal = __ballot_sync(0xffffffffu, p);
        if (lane == 0) s_warp[warp] = __popc(bal);
        __syncthreads();
        int woff = 0, tot = 0;
        for (int w = 0; w < 8; w++) { if (w < warp) woff += s_warp[w]; tot += s_warp[w]; }
        const int rank = __popc(bal & ((1u << lane) - 1u));
        if (p) idx[e * NTOK + s_base + woff + rank] = t;
        __syncthreads();
        if (threadIdx.x == 0) s_base += tot;
        __syncthreads();
    }
    if (threadIdx.x == 0) cnt[e] = s_base;
}

__global__ void silu_mul_kernel(const float* __restrict__ h1,
                                const float* __restrict__ h2,
                                float* __restrict__ out,
                                int width, const int* __restrict__ mcnt)
{
    const long total = (long)(mcnt ? *mcnt : NTOK) * width;
    const long stride = (long)gridDim.x * blockDim.x;
    for (long i = (long)blockIdx.x * blockDim.x + threadIdx.x; i < total; i += stride) {
        const float a = h1[i];
        const float s = a / (1.f + expf(-a));
        out[i] = s * h2[i];
    }
}

__global__ void zero_kernel(float* __restrict__ out, long n)
{
    const long stride = (long)gridDim.x * blockDim.x;
    for (long i = (long)blockIdx.x * blockDim.x + threadIdx.x; i < n; i += stride)
        out[i] = 0.f;
}

// ---------------- launcher ---------------------------------------------------
extern "C" void kernel_launch(void* const* d_in, const int* in_sizes, int n_in,
                              void* d_out, int out_size)
{
    const float* x       = (const float*)d_in[0];
    const float* r_in_w  = (const float*)d_in[1];
    const float* r_in_b  = (const float*)d_in[2];
    const float* rs_w1   = (const float*)d_in[3];
    const float* rs_b1   = (const float*)d_in[4];
    const float* rs_w2   = (const float*)d_in[5];
    const float* rs_b2   = (const float*)d_in[6];
    const float* rs_w3   = (const float*)d_in[7];
    const float* rs_b3   = (const float*)d_in[8];
    const float* r_out_w = (const float*)d_in[9];
    const float* r_out_b = (const float*)d_in[10];
    const float* e_in_w  = (const float*)d_in[11];
    const float* e_in_b  = (const float*)d_in[12];
    const float* es_w1   = (const float*)d_in[13];
    const float* es_b1   = (const float*)d_in[14];
    const float* es_w2   = (const float*)d_in[15];
    const float* es_b2   = (const float*)d_in[16];
    const float* es_w3   = (const float*)d_in[17];
    const float* es_b3   = (const float*)d_in[18];
    const float* e_out_w = (const float*)d_in[19];
    const float* e_out_b = (const float*)d_in[20];
    float* out = (float*)d_out;

    float *bufA, *bufB, *bufC, *logits;
    unsigned* maskb;
    int *idx, *cnt;
    cudaGetSymbolAddress((void**)&bufA,   g_bufA);
    cudaGetSymbolAddress((void**)&bufB,   g_bufB);
    cudaGetSymbolAddress((void**)&bufC,   g_bufC);
    cudaGetSymbolAddress((void**)&logits, g_logits);
    cudaGetSymbolAddress((void**)&maskb,  g_mask);
    cudaGetSymbolAddress((void**)&idx,    g_idx);
    cudaGetSymbolAddress((void**)&cnt,    g_cnt);

    const dim3 blk(256);
    const dim3 gridRouter(RHM / 128, NTOK / 128);   // 8 x 128
    const dim3 gridRIn(RHM / 128, NTOK / 128);
    const dim3 gridEH(HM / 128, NTOK / 128);        // 16 x 128
    const dim3 gridEO(DM / 128, NTOK / 128);        // 4 x 128

    // ---- router ----
    mma_gemm_kernel<false, false><<<gridRIn, blk>>>(x, r_in_w, r_in_b, bufA,
                                                    DM, RHM, nullptr, nullptr, 1.f);
    mma_gemm_kernel<false, false><<<gridRouter, blk>>>(bufA, rs_w1, rs_b1, bufB,
                                                       RHM, RHM, nullptr, nullptr, 1.f);
    mma_gemm_kernel<false, false><<<gridRouter, blk>>>(bufA, rs_w2, rs_b2, bufC,
                                                       RHM, RHM, nullptr, nullptr, 1.f);
    silu_mul_kernel<<<2048, blk>>>(bufB, bufC, bufB, RHM, nullptr);
    mma_gemm_kernel<false, false><<<gridRouter, blk>>>(bufB, rs_w3, rs_b3, bufA,
                                                       RHM, RHM, nullptr, nullptr, 1.f);
    logits_kernel<<<NTOK, blk>>>(bufA, r_out_w, r_out_b, logits);
    topk_kernel<<<NTOK / 256, blk>>>(logits, maskb);
    compact_kernel<<<EM, blk>>>(maskb, idx, cnt);

    // ---- output init ----
    zero_kernel<<<1024, blk>>>(out, (long)NTOK * DM);

    // ---- experts (selected tokens only) ----
    for (int e = 0; e < EM; e++) {
        const int* ce = cnt + e;
        const int* ie = idx + e * NTOK;
        mma_gemm_kernel<true, false><<<gridEH, blk>>>(
            x, e_in_w + (long)e * DM * HM, e_in_b + (long)e * HM, bufA,
            DM, HM, ce, ie, 1.f);
        mma_gemm_kernel<false, false><<<gridEH, blk>>>(
            bufA, es_w1 + (long)e * HM * HM, es_b1 + (long)e * HM, bufB,
            HM, HM, ce, nullptr, 1.f);
        mma_gemm_kernel<false, false><<<gridEH, blk>>>(
            bufA, es_w2 + (long)e * HM * HM, es_b2 + (long)e * HM, bufC,
            HM, HM, ce, nullptr, 1.f);
        silu_mul_kernel<<<2048, blk>>>(bufB, bufC, bufB, HM, ce);
        mma_gemm_kernel<false, false><<<gridEH, blk>>>(
            bufB, es_w3 + (long)e * HM * HM, es_b3 + (long)e * HM, bufA,
            HM, HM, ce, nullptr, 1.f);
        mma_gemm_kernel<false, true><<<gridEO, blk>>>(
            bufA, e_out_w + (long)e * HM * DM, e_out_b + (long)e * DM, out,
            HM, DM, ce, ie, 1.f / EM);
    }
}